// round 15
// baseline (speedup 1.0000x reference)
#include <cuda_runtime.h>
#include <cuda_bf16.h>
#include <cstdint>

#define N_ROWS 131072
#define D      64
#define KFULL  1024
#define KM1    1023
#define TPB    128
#define BTPB   256
#define ROWS_PER_CTA 128
#define CHUNK  64
#define NCHUNK (KFULL / CHUNK)
#define BSTR   72            // padded bf16 stride per code row (conflict-free)
#define KEYMASK 0xFFFFFC00
#define ESTR   66            // padded float stride for z staging

// device scratch (no dynamic allocation allowed)
__device__ float          g_dith[KFULL * D];   // exact dithered codebook
__device__ __nv_bfloat16  g_dhb[KFULL * D];    // bf16 hi
__device__ float          g_cj[KFULL];         // exact ||d||^2; [1023]=1e30
__device__ float          g_cjq[KFULL];        // cj + 0.75 (key bias); [1023]=0.95
__device__ int            g_counts[KFULL];
__device__ int            g_cand[N_ROWS * 12]; // 12 packed candidate keys per row
__device__ int            g_idx[N_ROWS];       // chosen index per row
__device__ unsigned       g_done;

// ---------------- helpers ----------------
__device__ __forceinline__ uint32_t bfpack2(float2 v) {
    uint32_t r;
    asm("cvt.rn.bf16x2.f32 %0, %1, %2;" : "=r"(r) : "f"(v.y), "f"(v.x));
    return r;
}
__device__ __forceinline__ void mma16(float* d, const uint32_t* a,
                                      uint32_t b0, uint32_t b1) {
    asm volatile(
        "mma.sync.aligned.m16n8k16.row.col.f32.bf16.bf16.f32 "
        "{%0,%1,%2,%3}, {%4,%5,%6,%7}, {%8,%9}, {%0,%1,%2,%3};"
        : "+f"(d[0]), "+f"(d[1]), "+f"(d[2]), "+f"(d[3])
        : "r"(a[0]), "r"(a[1]), "r"(a[2]), "r"(a[3]), "r"(b0), "r"(b1));
}
// branchless merge of pair into sorted top-3 (m0<=m1<=m2)
__device__ __forceinline__ void merge3(int& m0, int& m1, int& m2,
                                       int k0, int k1) {
    int klo = min(k0, k1);
    int khi = max(k0, k1);
    int r0 = min(m0, klo);
    int x  = max(m0, klo);
    int r1 = min(min(x, m1), khi);
    int mk = min(m1, khi);
    int Mk = max(m1, khi);
    int xm = max(x, mk);
    int r2 = min(min(Mk, xm), m2);
    m0 = r0; m1 = r1; m2 = r2;
}

// ---------- prep 1: elementwise dithered codebook + bf16 hi ----------
__global__ void split_kernel(const float* __restrict__ cb,
                             const float* __restrict__ dither) {
    int idx = blockIdx.x * blockDim.x + threadIdx.x;
    if (idx >= KFULL * D) return;
    int j = idx >> 6;
    float dv = 0.0f;
    if (j < KM1) {
        int k = idx & 63;
        float lo = cb[j * D + k];
        float hi = cb[(j + 1) * D + k];
        dv = __fadd_rn(lo, __fmul_rn(dither[j], __fsub_rn(hi, lo)));
    }
    g_dith[idx] = dv;
    g_dhb[idx] = __float2bfloat16_rn(dv);
    if (idx < KFULL) g_counts[idx] = 0;
    if (idx == 0) g_done = 0u;
}

// ---------- prep 2: ||d_j||^2 locked sequential + key bias ----------
__global__ void cj_kernel() {
    int j = blockIdx.x * blockDim.x + threadIdx.x;
    if (j >= KFULL) return;
    if (j >= KM1) { g_cj[j] = 1e30f; g_cjq[j] = 0.95f; return; }
    float acc = 0.0f;
    #pragma unroll 8
    for (int k = 0; k < D; k++) {
        float d = g_dith[j * D + k];
        acc = __fadd_rn(acc, __fmul_rn(d, d));
    }
    g_cj[j] = acc;
    g_cjq[j] = acc + 0.75f;
}

// ---------- prefilter: bf16 mma + packed-key top-3 -> g_cand ----------
__global__ void __launch_bounds__(TPB, 4)
prefilter_kernel(const float* __restrict__ z) {
    __shared__ __align__(16) __nv_bfloat16 sh_bh[2][CHUNK * BSTR];  // 18432 B
    __shared__ float sh_cq[2][CHUNK];

    const int tid  = threadIdx.x;
    const int w    = tid >> 5;
    const int lane = tid & 31;
    const int g    = lane >> 2;
    const int tig  = lane & 3;

    const float* zb = z + (size_t)(blockIdx.x * ROWS_PER_CTA + w * 32) * D;
    uint32_t ah[2][4][4];
    #pragma unroll
    for (int m = 0; m < 2; m++) {
        #pragma unroll
        for (int s = 0; s < 4; s++) {
            int r0 = m * 16 + g, r1 = r0 + 8;
            int kb = s * 16 + tig * 2;
            ah[m][s][0] = bfpack2(*(const float2*)(zb + r0 * D + kb));
            ah[m][s][1] = bfpack2(*(const float2*)(zb + r1 * D + kb));
            ah[m][s][2] = bfpack2(*(const float2*)(zb + r0 * D + kb + 8));
            ah[m][s][3] = bfpack2(*(const float2*)(zb + r1 * D + kb + 8));
        }
    }

    int m0[4], m1[4], m2[4];
    #pragma unroll
    for (int r = 0; r < 4; r++) { m0[r] = 0x7FFFFFFF; m1[r] = 0x7FFFFFFF; m2[r] = 0x7FFFFFFF; }

    {
        const uint2* srcH = (const uint2*)g_dhb;
        #pragma unroll
        for (int i = 0; i < 8; i++) {
            int q = tid + i * TPB;
            *(uint2*)(&sh_bh[0][(q >> 4) * BSTR + (q & 15) * 4]) = srcH[q];
        }
        if (tid < CHUNK) sh_cq[0][tid] = g_cjq[tid];
    }
    __syncthreads();

    for (int ch = 0; ch < NCHUNK; ch++) {
        const int cur = ch & 1;
        const int base = ch * CHUNK;

        uint2 rH[8];
        float rc = 0.0f;
        if (ch + 1 < NCHUNK) {
            const uint2* srcH = (const uint2*)(g_dhb + (size_t)(ch + 1) * CHUNK * D);
            #pragma unroll
            for (int i = 0; i < 8; i++) rH[i] = srcH[tid + i * TPB];
            if (tid < CHUNK) rc = g_cjq[(ch + 1) * CHUNK + tid];
        }

        #pragma unroll
        for (int t = 0; t < 8; t++) {
            float acc0[4] = {0.f, 0.f, 0.f, 0.f};
            float acc1[4] = {0.f, 0.f, 0.f, 0.f};
            #pragma unroll
            for (int s = 0; s < 4; s++) {
                const __nv_bfloat16* bp = &sh_bh[cur][(t * 8 + g) * BSTR + s * 16 + tig * 2];
                uint32_t bh0 = *(const uint32_t*)bp;
                uint32_t bh1 = *(const uint32_t*)(bp + 8);
                mma16(acc0, ah[0][s], bh0, bh1);
                mma16(acc1, ah[1][s], bh0, bh1);
            }
            const int j0 = base + t * 8 + tig * 2;
            const float cq0 = sh_cq[cur][t * 8 + tig * 2];
            const float cq1 = sh_cq[cur][t * 8 + tig * 2 + 1];
            int k00 = (__float_as_int(__fmaf_rn(-2.f, acc0[0], cq0)) & KEYMASK) | j0;
            int k01 = (__float_as_int(__fmaf_rn(-2.f, acc0[1], cq1)) & KEYMASK) | (j0 + 1);
            int k02 = (__float_as_int(__fmaf_rn(-2.f, acc0[2], cq0)) & KEYMASK) | j0;
            int k03 = (__float_as_int(__fmaf_rn(-2.f, acc0[3], cq1)) & KEYMASK) | (j0 + 1);
            int k10 = (__float_as_int(__fmaf_rn(-2.f, acc1[0], cq0)) & KEYMASK) | j0;
            int k11 = (__float_as_int(__fmaf_rn(-2.f, acc1[1], cq1)) & KEYMASK) | (j0 + 1);
            int k12 = (__float_as_int(__fmaf_rn(-2.f, acc1[2], cq0)) & KEYMASK) | j0;
            int k13 = (__float_as_int(__fmaf_rn(-2.f, acc1[3], cq1)) & KEYMASK) | (j0 + 1);
            merge3(m0[0], m1[0], m2[0], k00, k01);
            merge3(m0[1], m1[1], m2[1], k02, k03);
            merge3(m0[2], m1[2], m2[2], k10, k11);
            merge3(m0[3], m1[3], m2[3], k12, k13);
        }

        if (ch + 1 < NCHUNK) {
            const int nxt = cur ^ 1;
            #pragma unroll
            for (int i = 0; i < 8; i++) {
                int q = tid + i * TPB;
                *(uint2*)(&sh_bh[nxt][(q >> 4) * BSTR + (q & 15) * 4]) = rH[i];
            }
            if (tid < CHUNK) sh_cq[nxt][tid] = rc;
        }
        __syncthreads();
    }

    #pragma unroll
    for (int r = 0; r < 4; r++) {
        int lrow = w * 32 + (r >> 1) * 16 + (r & 1) * 8 + g;
        int bb = (blockIdx.x * ROWS_PER_CTA + lrow) * 12 + tig * 3;
        g_cand[bb + 0] = m0[r];
        g_cand[bb + 1] = m1[r];
        g_cand[bb + 2] = m2[r];
    }
}

// ---------- finalize A: locked rescore (thread-per-row) -> indices ----------
__global__ void __launch_bounds__(TPB, 6)
finalizeA_kernel(const float* __restrict__ z, float* __restrict__ out) {
    __shared__ __align__(16) float sz[TPB * ESTR];   // 33792 B

    const int tid = threadIdx.x;
    const int row = blockIdx.x * TPB + tid;
    const size_t blk = (size_t)blockIdx.x * TPB * D;

    // coalesced staging of z rows into padded shared
    {
        const float2* zp = (const float2*)(z + blk);
        #pragma unroll
        for (int i = 0; i < 32; i++) {
            int idx = tid + i * TPB;
            int r = idx >> 5, q = idx & 31;
            *(float2*)(sz + r * ESTR + q * 2) = zp[idx];
        }
    }
    __syncthreads();

    const float* zrow = sz + tid * ESTR;
    float nz = 0.0f;
    #pragma unroll
    for (int k = 0; k < D; k++) {
        float v = zrow[k];
        nz = __fadd_rn(nz, __fmul_rn(v, v));
    }

    int ck[12];
    #pragma unroll
    for (int k = 0; k < 12; k++) ck[k] = g_cand[row * 12 + k];

    int mink = 0x7FFFFFFF;
    #pragma unroll
    for (int k = 0; k < 12; k++) mink = min(mink, ck[k]);
    const float thrf = __int_as_float(mink & KEYMASK) + 4e-4f;

    float best = 3.4e38f;
    int   bj   = 0x7FFFFFFF;
    for (int k = 0; k < 12; k++) {
        if (__int_as_float(ck[k]) <= thrf) {
            int j = ck[k] & 1023;
            const float* dj = g_dith + (size_t)j * D;
            float c0 = 0.f, c1 = 0.f, c2 = 0.f, c3 = 0.f;
            float c4 = 0.f, c5 = 0.f, c6 = 0.f, c7 = 0.f;
            #pragma unroll
            for (int q = 0; q < D; q += 8) {
                c0 = __fmaf_rn(zrow[q + 0], dj[q + 0], c0);
                c1 = __fmaf_rn(zrow[q + 1], dj[q + 1], c1);
                c2 = __fmaf_rn(zrow[q + 2], dj[q + 2], c2);
                c3 = __fmaf_rn(zrow[q + 3], dj[q + 3], c3);
                c4 = __fmaf_rn(zrow[q + 4], dj[q + 4], c4);
                c5 = __fmaf_rn(zrow[q + 5], dj[q + 5], c5);
                c6 = __fmaf_rn(zrow[q + 6], dj[q + 6], c6);
                c7 = __fmaf_rn(zrow[q + 7], dj[q + 7], c7);
            }
            float dot = __fadd_rn(
                __fadd_rn(__fadd_rn(c0, c1), __fadd_rn(c2, c3)),
                __fadd_rn(__fadd_rn(c4, c5), __fadd_rn(c6, c7)));
            float s = __fsub_rn(__fadd_rn(nz, g_cj[j]), __fmul_rn(2.0f, dot));
            if (s < best || (s == best && j < bj)) { best = s; bj = j; }
        }
    }

    g_idx[row] = bj;
    out[(size_t)N_ROWS * D + row] = (float)bj;
    atomicAdd(&g_counts[bj], 1);
}

// ---------- finalize B: warp-per-row streaming epilogue + perplexity ----------
__global__ void __launch_bounds__(BTPB)
finalizeB_kernel(const float* __restrict__ z,
                 const float* __restrict__ cb,
                 const float* __restrict__ dither,
                 const float* __restrict__ n1,
                 const float* __restrict__ n2,
                 float* __restrict__ out) {
    __shared__ int   s_last;
    __shared__ float red[BTPB];

    const int tid  = threadIdx.x;
    const int w    = tid >> 5;                 // 8 warps
    const int lane = tid & 31;

    // CTA covers 128 rows: 8 warps x 16 rows
    const int rbase = blockIdx.x * 128 + w * 16;

    #pragma unroll 2
    for (int r = 0; r < 16; r++) {
        const int R = rbase + r;
        const int i = g_idx[R];

        float2 zz = ((const float2*)(z  + (size_t)R * D))[lane];
        float2 av = ((const float2*)(n1 + (size_t)R * D))[lane];
        float2 bv = ((const float2*)(n2 + (size_t)R * D))[lane];
        float2 cf = ((const float2*)(cb + (size_t)i * D))[lane];
        float2 cs = ((const float2*)(cb + (size_t)(i + 1) * D))[lane];

        float d1x = __fsub_rn(cf.x, zz.x), d1y = __fsub_rn(cf.y, zz.y);
        float r1x = __fadd_rn(av.x, d1x),  r1y = __fadd_rn(av.y, d1y);
        float d2x = __fsub_rn(cs.x, zz.x), d2y = __fsub_rn(cs.y, zz.y);
        float r2x = __fadd_rn(bv.x, d2x),  r2y = __fadd_rn(bv.y, d2y);

        float sd1 = __fadd_rn(__fmul_rn(d1x, d1x), __fmul_rn(d1y, d1y));
        float sr1 = __fadd_rn(__fmul_rn(r1x, r1x), __fmul_rn(r1y, r1y));
        float sd2 = __fadd_rn(__fmul_rn(d2x, d2x), __fmul_rn(d2y, d2y));
        float sr2 = __fadd_rn(__fmul_rn(r2x, r2x), __fmul_rn(r2y, r2y));

        #pragma unroll
        for (int off = 16; off > 0; off >>= 1) {
            sd1 = __fadd_rn(sd1, __shfl_xor_sync(0xFFFFFFFFu, sd1, off));
            sr1 = __fadd_rn(sr1, __shfl_xor_sync(0xFFFFFFFFu, sr1, off));
            sd2 = __fadd_rn(sd2, __shfl_xor_sync(0xFFFFFFFFu, sd2, off));
            sr2 = __fadd_rn(sr2, __shfl_xor_sync(0xFFFFFFFFu, sr2, off));
        }

        float lam = dither[i];
        float nn1 = fmaxf(__fsqrt_rn(sr1), 1e-12f);
        float nn2 = fmaxf(__fsqrt_rn(sr2), 1e-12f);
        float em1 = __fsqrt_rn(sd1);
        float em2 = __fsqrt_rn(sd2);
        float s1  = __fsub_rn(1.0f, lam);

        float2 o;
        {
            float v1 = __fmul_rn(em1, __fmul_rn(s1,  __fdiv_rn(r1x, nn1)));
            float v2 = __fmul_rn(em2, __fmul_rn(lam, __fdiv_rn(r2x, nn2)));
            o.x = __fadd_rn(__fadd_rn(zz.x, v1), v2);
        }
        {
            float v1 = __fmul_rn(em1, __fmul_rn(s1,  __fdiv_rn(r1y, nn1)));
            float v2 = __fmul_rn(em2, __fmul_rn(lam, __fdiv_rn(r2y, nn2)));
            o.y = __fadd_rn(__fadd_rn(zz.y, v1), v2);
        }
        ((float2*)(out + (size_t)R * D))[lane] = o;
    }

    // ---------- fused perplexity: last CTA reduces ----------
    __threadfence();
    __syncthreads();
    if (tid == 0) {
        unsigned v = atomicAdd(&g_done, 1u);
        s_last = (v == (unsigned)(gridDim.x - 1)) ? 1 : 0;
    }
    __syncthreads();
    if (s_last) {
        float part = 0.0f;
        #pragma unroll
        for (int t = tid; t < KFULL; t += BTPB) {
            float p = (float)__ldcg(&g_counts[t]) * (1.0f / 131072.0f);
            part = __fadd_rn(part, (p > 0.0f) ? __fmul_rn(p, logf(p)) : 0.0f);
        }
        red[tid] = part;
        __syncthreads();
        for (int s = BTPB / 2; s > 0; s >>= 1) {
            if (tid < s) red[tid] = __fadd_rn(red[tid], red[tid + s]);
            __syncthreads();
        }
        if (tid == 0) out[(size_t)N_ROWS * D + N_ROWS] = expf(-red[0]);
    }
}

extern "C" void kernel_launch(void* const* d_in, const int* in_sizes, int n_in,
                              void* d_out, int out_size) {
    const float* z      = (const float*)d_in[0];
    const float* cb     = (const float*)d_in[1];
    const float* dither = (const float*)d_in[2];
    const float* n1     = (const float*)d_in[3];
    const float* n2     = (const float*)d_in[4];
    float* out = (float*)d_out;

    split_kernel<<<(KFULL * D + 255) / 256, 256>>>(cb, dither);
    cj_kernel<<<KFULL / 128, 128>>>();
    prefilter_kernel<<<N_ROWS / ROWS_PER_CTA, TPB>>>(z);
    finalizeA_kernel<<<N_ROWS / TPB, TPB>>>(z, out);
    finalizeB_kernel<<<N_ROWS / 128, BTPB>>>(z, cb, dither, n1, n2, out);
}

// round 16
// speedup vs baseline: 1.1917x; 1.1917x over previous
#include <cuda_runtime.h>
#include <cuda_bf16.h>
#include <cstdint>

#define N_ROWS 131072
#define D      64
#define KFULL  1024
#define KM1    1023
#define TPB    128
#define ROWS_PER_CTA 128
#define CHUNK  64
#define NCHUNK (KFULL / CHUNK)
#define BSTR   72            // padded bf16 stride per code row (conflict-free)
#define KEYMASK 0xFFFFFC00
#define ESTR   66            // padded float stride for z staging

// device scratch (no dynamic allocation allowed)
__device__ float          g_dith[KFULL * D];   // exact dithered codebook
__device__ __nv_bfloat16  g_dhb[KFULL * D];    // bf16 hi
__device__ float          g_cj[KFULL];         // exact ||d||^2; [1023]=1e30
__device__ float          g_cjq[KFULL];        // cj + 0.75 (key bias); [1023]=0.95
__device__ int            g_counts[KFULL];
__device__ int            g_cand[N_ROWS * 12]; // 12 packed candidate keys per row
__device__ unsigned       g_done;

// ---------------- helpers ----------------
__device__ __forceinline__ uint32_t bfpack2(float2 v) {
    uint32_t r;
    asm("cvt.rn.bf16x2.f32 %0, %1, %2;" : "=r"(r) : "f"(v.y), "f"(v.x));
    return r;
}
__device__ __forceinline__ void mma16(float* d, const uint32_t* a,
                                      uint32_t b0, uint32_t b1) {
    asm volatile(
        "mma.sync.aligned.m16n8k16.row.col.f32.bf16.bf16.f32 "
        "{%0,%1,%2,%3}, {%4,%5,%6,%7}, {%8,%9}, {%0,%1,%2,%3};"
        : "+f"(d[0]), "+f"(d[1]), "+f"(d[2]), "+f"(d[3])
        : "r"(a[0]), "r"(a[1]), "r"(a[2]), "r"(a[3]), "r"(b0), "r"(b1));
}
// branchless merge of pair into sorted top-3 (m0<=m1<=m2)
__device__ __forceinline__ void merge3(int& m0, int& m1, int& m2,
                                       int k0, int k1) {
    int klo = min(k0, k1);
    int khi = max(k0, k1);
    int r0 = min(m0, klo);
    int x  = max(m0, klo);
    int r1 = min(min(x, m1), khi);
    int mk = min(m1, khi);
    int Mk = max(m1, khi);
    int xm = max(x, mk);
    int r2 = min(min(Mk, xm), m2);
    m0 = r0; m1 = r1; m2 = r2;
}

// ---------- prep 1: elementwise dithered codebook + bf16 hi ----------
__global__ void split_kernel(const float* __restrict__ cb,
                             const float* __restrict__ dither) {
    int idx = blockIdx.x * blockDim.x + threadIdx.x;
    if (idx >= KFULL * D) return;
    int j = idx >> 6;
    float dv = 0.0f;
    if (j < KM1) {
        int k = idx & 63;
        float lo = cb[j * D + k];
        float hi = cb[(j + 1) * D + k];
        dv = __fadd_rn(lo, __fmul_rn(dither[j], __fsub_rn(hi, lo)));
    }
    g_dith[idx] = dv;
    g_dhb[idx] = __float2bfloat16_rn(dv);
    if (idx < KFULL) g_counts[idx] = 0;
    if (idx == 0) g_done = 0u;
}

// ---------- prep 2: ||d_j||^2 locked sequential + key bias ----------
__global__ void cj_kernel() {
    int j = blockIdx.x * blockDim.x + threadIdx.x;
    if (j >= KFULL) return;
    if (j >= KM1) { g_cj[j] = 1e30f; g_cjq[j] = 0.95f; return; }
    float acc = 0.0f;
    #pragma unroll 8
    for (int k = 0; k < D; k++) {
        float d = g_dith[j * D + k];
        acc = __fadd_rn(acc, __fmul_rn(d, d));
    }
    g_cj[j] = acc;
    g_cjq[j] = acc + 0.75f;
}

// ---------- prefilter: bf16 mma + packed-key top-3 -> g_cand ----------
__global__ void __launch_bounds__(TPB, 4)
prefilter_kernel(const float* __restrict__ z) {
    __shared__ __align__(16) __nv_bfloat16 sh_bh[2][CHUNK * BSTR];  // 18432 B
    __shared__ float sh_cq[2][CHUNK];

    const int tid  = threadIdx.x;
    const int w    = tid >> 5;
    const int lane = tid & 31;
    const int g    = lane >> 2;
    const int tig  = lane & 3;

    const float* zb = z + (size_t)(blockIdx.x * ROWS_PER_CTA + w * 32) * D;
    uint32_t ah[2][4][4];
    #pragma unroll
    for (int m = 0; m < 2; m++) {
        #pragma unroll
        for (int s = 0; s < 4; s++) {
            int r0 = m * 16 + g, r1 = r0 + 8;
            int kb = s * 16 + tig * 2;
            ah[m][s][0] = bfpack2(*(const float2*)(zb + r0 * D + kb));
            ah[m][s][1] = bfpack2(*(const float2*)(zb + r1 * D + kb));
            ah[m][s][2] = bfpack2(*(const float2*)(zb + r0 * D + kb + 8));
            ah[m][s][3] = bfpack2(*(const float2*)(zb + r1 * D + kb + 8));
        }
    }

    int m0[4], m1[4], m2[4];
    #pragma unroll
    for (int r = 0; r < 4; r++) { m0[r] = 0x7FFFFFFF; m1[r] = 0x7FFFFFFF; m2[r] = 0x7FFFFFFF; }

    {
        const uint2* srcH = (const uint2*)g_dhb;
        #pragma unroll
        for (int i = 0; i < 8; i++) {
            int q = tid + i * TPB;
            *(uint2*)(&sh_bh[0][(q >> 4) * BSTR + (q & 15) * 4]) = srcH[q];
        }
        if (tid < CHUNK) sh_cq[0][tid] = g_cjq[tid];
    }
    __syncthreads();

    for (int ch = 0; ch < NCHUNK; ch++) {
        const int cur = ch & 1;
        const int base = ch * CHUNK;

        uint2 rH[8];
        float rc = 0.0f;
        if (ch + 1 < NCHUNK) {
            const uint2* srcH = (const uint2*)(g_dhb + (size_t)(ch + 1) * CHUNK * D);
            #pragma unroll
            for (int i = 0; i < 8; i++) rH[i] = srcH[tid + i * TPB];
            if (tid < CHUNK) rc = g_cjq[(ch + 1) * CHUNK + tid];
        }

        #pragma unroll
        for (int t = 0; t < 8; t++) {
            float acc0[4] = {0.f, 0.f, 0.f, 0.f};
            float acc1[4] = {0.f, 0.f, 0.f, 0.f};
            #pragma unroll
            for (int s = 0; s < 4; s++) {
                const __nv_bfloat16* bp = &sh_bh[cur][(t * 8 + g) * BSTR + s * 16 + tig * 2];
                uint32_t bh0 = *(const uint32_t*)bp;
                uint32_t bh1 = *(const uint32_t*)(bp + 8);
                mma16(acc0, ah[0][s], bh0, bh1);
                mma16(acc1, ah[1][s], bh0, bh1);
            }
            const int j0 = base + t * 8 + tig * 2;
            const float cq0 = sh_cq[cur][t * 8 + tig * 2];
            const float cq1 = sh_cq[cur][t * 8 + tig * 2 + 1];
            int k00 = (__float_as_int(__fmaf_rn(-2.f, acc0[0], cq0)) & KEYMASK) | j0;
            int k01 = (__float_as_int(__fmaf_rn(-2.f, acc0[1], cq1)) & KEYMASK) | (j0 + 1);
            int k02 = (__float_as_int(__fmaf_rn(-2.f, acc0[2], cq0)) & KEYMASK) | j0;
            int k03 = (__float_as_int(__fmaf_rn(-2.f, acc0[3], cq1)) & KEYMASK) | (j0 + 1);
            int k10 = (__float_as_int(__fmaf_rn(-2.f, acc1[0], cq0)) & KEYMASK) | j0;
            int k11 = (__float_as_int(__fmaf_rn(-2.f, acc1[1], cq1)) & KEYMASK) | (j0 + 1);
            int k12 = (__float_as_int(__fmaf_rn(-2.f, acc1[2], cq0)) & KEYMASK) | j0;
            int k13 = (__float_as_int(__fmaf_rn(-2.f, acc1[3], cq1)) & KEYMASK) | (j0 + 1);
            merge3(m0[0], m1[0], m2[0], k00, k01);
            merge3(m0[1], m1[1], m2[1], k02, k03);
            merge3(m0[2], m1[2], m2[2], k10, k11);
            merge3(m0[3], m1[3], m2[3], k12, k13);
        }

        if (ch + 1 < NCHUNK) {
            const int nxt = cur ^ 1;
            #pragma unroll
            for (int i = 0; i < 8; i++) {
                int q = tid + i * TPB;
                *(uint2*)(&sh_bh[nxt][(q >> 4) * BSTR + (q & 15) * 4]) = rH[i];
            }
            if (tid < CHUNK) sh_cq[nxt][tid] = rc;
        }
        __syncthreads();
    }

    #pragma unroll
    for (int r = 0; r < 4; r++) {
        int lrow = w * 32 + (r >> 1) * 16 + (r & 1) * 8 + g;
        int bb = (blockIdx.x * ROWS_PER_CTA + lrow) * 12 + tig * 3;
        g_cand[bb + 0] = m0[r];
        g_cand[bb + 1] = m1[r];
        g_cand[bb + 2] = m2[r];
    }
}

// ---------- finalize: shortcut rescore (thread/row) + warp-per-row epilogue ----------
__global__ void __launch_bounds__(TPB, 4)
finalize_kernel(const float* __restrict__ z,
                const float* __restrict__ cb,
                const float* __restrict__ dither,
                const float* __restrict__ n1,
                const float* __restrict__ n2,
                float* __restrict__ out) {
    __shared__ __align__(16) float sz[TPB * ESTR];   // 33792 B: z rows
    __shared__ int   sbj[TPB];
    __shared__ int   s_last;
    __shared__ float red[TPB];

    const int tid  = threadIdx.x;
    const int w    = tid >> 5;
    const int lane = tid & 31;
    const int row  = blockIdx.x * TPB + tid;
    const size_t blk = (size_t)blockIdx.x * TPB * D;

    // coalesced staging of z rows into padded shared
    {
        const float2* zp = (const float2*)(z + blk);
        #pragma unroll
        for (int i = 0; i < 32; i++) {
            int idx = tid + i * TPB;
            int r = idx >> 5, q = idx & 31;
            *(float2*)(sz + r * ESTR + q * 2) = zp[idx];
        }
    }
    __syncthreads();

    // ---------- Phase A: candidate count + (conditional) locked rescore ----------
    const float* zrow = sz + tid * ESTR;

    int ck[12];
    #pragma unroll
    for (int k = 0; k < 12; k++) ck[k] = g_cand[row * 12 + k];

    int mink = 0x7FFFFFFF;
    #pragma unroll
    for (int k = 0; k < 12; k++) mink = min(mink, ck[k]);
    const float thrf = __int_as_float(mink & KEYMASK) + 4e-4f;

    int ncand = 0;
    #pragma unroll
    for (int k = 0; k < 12; k++)
        ncand += (__int_as_float(ck[k]) <= thrf) ? 1 : 0;

    int bj;
    if (ncand == 1) {
        // only the min key is in the window: argmin decided, no gathers needed
        bj = mink & 1023;
    } else {
        // locked nz + locked rescore over in-window candidates
        float nz = 0.0f;
        #pragma unroll
        for (int k = 0; k < D; k++) {
            float v = zrow[k];
            nz = __fadd_rn(nz, __fmul_rn(v, v));
        }
        float best = 3.4e38f;
        bj = 0x7FFFFFFF;
        for (int k = 0; k < 12; k++) {
            if (__int_as_float(ck[k]) <= thrf) {
                int j = ck[k] & 1023;
                const float* dj = g_dith + (size_t)j * D;
                float c0 = 0.f, c1 = 0.f, c2 = 0.f, c3 = 0.f;
                float c4 = 0.f, c5 = 0.f, c6 = 0.f, c7 = 0.f;
                #pragma unroll
                for (int q = 0; q < D; q += 8) {
                    c0 = __fmaf_rn(zrow[q + 0], dj[q + 0], c0);
                    c1 = __fmaf_rn(zrow[q + 1], dj[q + 1], c1);
                    c2 = __fmaf_rn(zrow[q + 2], dj[q + 2], c2);
                    c3 = __fmaf_rn(zrow[q + 3], dj[q + 3], c3);
                    c4 = __fmaf_rn(zrow[q + 4], dj[q + 4], c4);
                    c5 = __fmaf_rn(zrow[q + 5], dj[q + 5], c5);
                    c6 = __fmaf_rn(zrow[q + 6], dj[q + 6], c6);
                    c7 = __fmaf_rn(zrow[q + 7], dj[q + 7], c7);
                }
                float dot = __fadd_rn(
                    __fadd_rn(__fadd_rn(c0, c1), __fadd_rn(c2, c3)),
                    __fadd_rn(__fadd_rn(c4, c5), __fadd_rn(c6, c7)));
                float s = __fsub_rn(__fadd_rn(nz, g_cj[j]), __fmul_rn(2.0f, dot));
                if (s < best || (s == best && j < bj)) { best = s; bj = j; }
            }
        }
    }
    sbj[tid] = bj;
    out[(size_t)N_ROWS * D + row] = (float)bj;
    atomicAdd(&g_counts[bj], 1);
    __syncthreads();

    // ---------- Phase B: warp-per-row epilogue (coalesced; tree-reduced sums) ----------
    for (int r = 0; r < 32; r++) {
        const int lrow = w * 32 + r;                       // row within CTA
        const int R    = blockIdx.x * TPB + lrow;          // global row
        const int i    = sbj[lrow];

        float2 zz = *(const float2*)(sz + lrow * ESTR + 2 * lane);
        float2 av = ((const float2*)(n1 + (size_t)R * D))[lane];
        float2 bv = ((const float2*)(n2 + (size_t)R * D))[lane];
        float2 cf = ((const float2*)(cb + (size_t)i * D))[lane];
        float2 cs = ((const float2*)(cb + (size_t)(i + 1) * D))[lane];

        float d1x = __fsub_rn(cf.x, zz.x), d1y = __fsub_rn(cf.y, zz.y);
        float r1x = __fadd_rn(av.x, d1x),  r1y = __fadd_rn(av.y, d1y);
        float d2x = __fsub_rn(cs.x, zz.x), d2y = __fsub_rn(cs.y, zz.y);
        float r2x = __fadd_rn(bv.x, d2x),  r2y = __fadd_rn(bv.y, d2y);

        float sd1 = __fadd_rn(__fmul_rn(d1x, d1x), __fmul_rn(d1y, d1y));
        float sr1 = __fadd_rn(__fmul_rn(r1x, r1x), __fmul_rn(r1y, r1y));
        float sd2 = __fadd_rn(__fmul_rn(d2x, d2x), __fmul_rn(d2y, d2y));
        float sr2 = __fadd_rn(__fmul_rn(r2x, r2x), __fmul_rn(r2y, r2y));

        #pragma unroll
        for (int off = 16; off > 0; off >>= 1) {
            sd1 = __fadd_rn(sd1, __shfl_xor_sync(0xFFFFFFFFu, sd1, off));
            sr1 = __fadd_rn(sr1, __shfl_xor_sync(0xFFFFFFFFu, sr1, off));
            sd2 = __fadd_rn(sd2, __shfl_xor_sync(0xFFFFFFFFu, sd2, off));
            sr2 = __fadd_rn(sr2, __shfl_xor_sync(0xFFFFFFFFu, sr2, off));
        }

        float lam = dither[i];
        float nn1 = fmaxf(__fsqrt_rn(sr1), 1e-12f);
        float nn2 = fmaxf(__fsqrt_rn(sr2), 1e-12f);
        float em1 = __fsqrt_rn(sd1);
        float em2 = __fsqrt_rn(sd2);
        float s1  = __fsub_rn(1.0f, lam);

        float2 o;
        {
            float v1 = __fmul_rn(em1, __fmul_rn(s1,  __fdiv_rn(r1x, nn1)));
            float v2 = __fmul_rn(em2, __fmul_rn(lam, __fdiv_rn(r2x, nn2)));
            o.x = __fadd_rn(__fadd_rn(zz.x, v1), v2);
        }
        {
            float v1 = __fmul_rn(em1, __fmul_rn(s1,  __fdiv_rn(r1y, nn1)));
            float v2 = __fmul_rn(em2, __fmul_rn(lam, __fdiv_rn(r2y, nn2)));
            o.y = __fadd_rn(__fadd_rn(zz.y, v1), v2);
        }
        ((float2*)(out + (size_t)R * D))[lane] = o;
    }

    // ---------- fused perplexity: last CTA reduces ----------
    __threadfence();
    __syncthreads();
    if (tid == 0) {
        unsigned v = atomicAdd(&g_done, 1u);
        s_last = (v == (unsigned)(gridDim.x - 1)) ? 1 : 0;
    }
    __syncthreads();
    if (s_last) {
        float part = 0.0f;
        #pragma unroll
        for (int t = tid; t < KFULL; t += TPB) {
            float p = (float)__ldcg(&g_counts[t]) * (1.0f / 131072.0f);
            part = __fadd_rn(part, (p > 0.0f) ? __fmul_rn(p, logf(p)) : 0.0f);
        }
        red[tid] = part;
        __syncthreads();
        for (int s = TPB / 2; s > 0; s >>= 1) {
            if (tid < s) red[tid] = __fadd_rn(red[tid], red[tid + s]);
            __syncthreads();
        }
        if (tid == 0) out[(size_t)N_ROWS * D + N_ROWS] = expf(-red[0]);
    }
}

extern "C" void kernel_launch(void* const* d_in, const int* in_sizes, int n_in,
                              void* d_out, int out_size) {
    const float* z      = (const float*)d_in[0];
    const float* cb     = (const float*)d_in[1];
    const float* dither = (const float*)d_in[2];
    const float* n1     = (const float*)d_in[3];
    const float* n2     = (const float*)d_in[4];
    float* out = (float*)d_out;

    split_kernel<<<(KFULL * D + 255) / 256, 256>>>(cb, dither);
    cj_kernel<<<KFULL / 128, 128>>>();
    prefilter_kernel<<<N_ROWS / ROWS_PER_CTA, TPB>>>(z);
    finalize_kernel<<<N_ROWS / TPB, TPB>>>(z, cb, dither, n1, n2, out);
}